// round 7
// baseline (speedup 1.0000x reference)
#include <cuda_runtime.h>
#include <math.h>

// ---------------- problem constants ----------------
#define BN     8      // batch
#define NN     1024   // seq len
#define DD     512    // model dim
#define HH     8      // heads
#define DHD    64     // dim per head
#define NHASH  4      // hash rounds
#define NBUCK  256    // buckets per round (N / BUCKET)
#define BSZ    4      // bucket size
#define BHN    (BN*HH)        // 64
#define MTOT   (BN*NN)        // 8192 rows for GEMMs
#define CHTOT  (NHASH*NBUCK)  // 1024 chunks per bh (flat, cross-round)

typedef unsigned long long ull;

// ---- packed f32x2 helpers (FFMA2 path; bit-exact fp32, 2 lanes/instr) ------
__device__ __forceinline__ ull pack2(float lo, float hi) {
    ull r; asm("mov.b64 %0, {%1, %2};" : "=l"(r) : "f"(lo), "f"(hi)); return r;
}
__device__ __forceinline__ void unpack2(ull v, float& lo, float& hi) {
    asm("mov.b64 {%0, %1}, %2;" : "=f"(lo), "=f"(hi) : "l"(v));
}
__device__ __forceinline__ void fma2(ull& d, ull a, ull b) {
    asm("fma.rn.f32x2 %0, %1, %2, %0;" : "+l"(d) : "l"(a), "l"(b));
}

// ---------------- scratch (device globals; no runtime alloc) ----------------
__device__ float g_qk    [BN*NN*DD];          // 16 MB
__device__ float g_v     [BN*NN*DD];          // 16 MB
__device__ int   g_bucket[BHN*NHASH*NN];      // 1 MB
__device__ int   g_st    [BHN*NHASH*NN];      // 1 MB
__device__ float g_o     [(size_t)BHN*NHASH*NN*DHD]; // 64 MB
__device__ float g_logits[BHN*NHASH*NN];      // 1 MB
__device__ float g_att   [BN*NN*DD];          // 16 MB

// ---------------- K1/K6: SGEMM 128x128, BK=8, FFMA2, dup-A smem, reg pp -----
// blockIdx.z selects (B0->C0) or (B1->C1) so qk- and v-GEMMs share one launch.
template<bool HASBIAS>
__global__ __launch_bounds__(256, 2) void sgemm128(
    const float* __restrict__ A,
    const float* __restrict__ B0p, const float* __restrict__ B1p,
    const float* __restrict__ bias,
    float* __restrict__ C0p, float* __restrict__ C1p,
    int M, int Nn, int K)
{
    __shared__ __align__(16) ull   As2[2][8][132];  // A pre-duplicated (a,a)
    __shared__ __align__(16) float Bs [2][8][132];
    const float* Bm = blockIdx.z ? B1p : B0p;
    float*       C  = blockIdx.z ? C1p : C0p;
    int tid = threadIdx.x;
    int bm = blockIdx.y * 128, bn = blockIdx.x * 128;
    int ty = tid >> 4, tx = tid & 15;

    int arow = tid >> 1;            // 0..127
    int akq  = (tid & 1) * 4;       // 0 or 4
    int bk   = tid >> 5;            // 0..7
    int bnq  = (tid & 31) * 4;      // 0..124

    const float* Aptr = A  + (size_t)(bm + arow) * K + akq;
    const float* Bptr = Bm + (size_t)bk * Nn + bn + bnq;

    ull acc[8][4];
    #pragma unroll
    for (int i = 0; i < 8; i++)
        #pragma unroll
        for (int jp = 0; jp < 4; jp++) acc[i][jp] = 0ull;

    float4 av = *(const float4*)(Aptr);
    float4 bv = *(const float4*)(Bptr);
    As2[0][akq+0][arow] = pack2(av.x, av.x);
    As2[0][akq+1][arow] = pack2(av.y, av.y);
    As2[0][akq+2][arow] = pack2(av.z, av.z);
    As2[0][akq+3][arow] = pack2(av.w, av.w);
    *(float4*)&Bs[0][bk][bnq] = bv;
    __syncthreads();

    int buf = 0;
    // register ping-pong prefetch state (lower-A rows + both B halves)
    ulonglong2 pfa0, pfa1, pfb0, pfb1;
    pfa0 = *(const ulonglong2*)&As2[buf][0][ty*4];
    pfa1 = *(const ulonglong2*)&As2[buf][0][ty*4+2];
    pfb0 = *(const ulonglong2*)&Bs [buf][0][tx*4];
    pfb1 = *(const ulonglong2*)&Bs [buf][0][64 + tx*4];

    for (int k0 = 8; k0 <= K; k0 += 8) {
        if (k0 < K) {
            av = *(const float4*)(Aptr + k0);
            bv = *(const float4*)(Bptr + (size_t)k0 * Nn);
        }
        #pragma unroll
        for (int k = 0; k < 8; k++) {
            ulonglong2 a0 = pfa0, a1 = pfa1, b0 = pfb0, b1 = pfb1;
            if (k < 7) {
                pfa0 = *(const ulonglong2*)&As2[buf][k+1][ty*4];
                pfa1 = *(const ulonglong2*)&As2[buf][k+1][ty*4+2];
                pfb0 = *(const ulonglong2*)&Bs [buf][k+1][tx*4];
                pfb1 = *(const ulonglong2*)&Bs [buf][k+1][64 + tx*4];
            }
            // upper-A rows at use (broadcast wavefronts, cheap)
            ulonglong2 a2 = *(const ulonglong2*)&As2[buf][k][64 + ty*4];
            ulonglong2 a3 = *(const ulonglong2*)&As2[buf][k][64 + ty*4+2];
            ull fa[8] = {a0.x, a0.y, a1.x, a1.y, a2.x, a2.y, a3.x, a3.y};
            #pragma unroll
            for (int i = 0; i < 8; i++) {
                fma2(acc[i][0], fa[i], b0.x);
                fma2(acc[i][1], fa[i], b0.y);
                fma2(acc[i][2], fa[i], b1.x);
                fma2(acc[i][3], fa[i], b1.y);
            }
        }
        if (k0 < K) {
            buf ^= 1;
            As2[buf][akq+0][arow] = pack2(av.x, av.x);
            As2[buf][akq+1][arow] = pack2(av.y, av.y);
            As2[buf][akq+2][arow] = pack2(av.z, av.z);
            As2[buf][akq+3][arow] = pack2(av.w, av.w);
            *(float4*)&Bs[buf][bk][bnq] = bv;
            __syncthreads();
            pfa0 = *(const ulonglong2*)&As2[buf][0][ty*4];
            pfa1 = *(const ulonglong2*)&As2[buf][0][ty*4+2];
            pfb0 = *(const ulonglong2*)&Bs [buf][0][tx*4];
            pfb1 = *(const ulonglong2*)&Bs [buf][0][64 + tx*4];
        }
    }

    #pragma unroll
    for (int rh = 0; rh < 2; rh++)
        #pragma unroll
        for (int i = 0; i < 4; i++) {
            int row = bm + rh*64 + ty*4 + i;
            #pragma unroll
            for (int ch = 0; ch < 2; ch++) {
                float4 o;
                unpack2(acc[rh*4+i][ch*2+0], o.x, o.y);
                unpack2(acc[rh*4+i][ch*2+1], o.z, o.w);
                int col = bn + ch*64 + tx*4;
                if (HASBIAS) {
                    o.x += bias[col+0]; o.y += bias[col+1];
                    o.z += bias[col+2]; o.w += bias[col+3];
                }
                *(float4*)(C + (size_t)row * Nn + col) = o;
            }
        }
}

// ---------------- K2: LSH hashing, FFMA2, 4 tok x 16 i per thread -----------
// Per-j accumulation chains identical to scalar version -> buckets bitwise same.
__global__ __launch_bounds__(128) void hash_kernel(const float* __restrict__ rot)
{
    __shared__ __align__(16) float qs[64][64];    // 16 KB
    __shared__ __align__(16) float rs[64][128];   // 32 KB
    int bh = blockIdx.y;
    int t0 = blockIdx.x * 64;
    int b = bh >> 3, h = bh & 7;
    int tid = threadIdx.x;
    int quad = tid >> 3, ig = tid & 7;

    for (int idx = tid; idx < 64*16; idx += 128) {
        int tk = idx >> 4, fq = (idx & 15) * 4;
        *(float4*)&qs[tk][fq] =
            *(const float4*)(g_qk + ((size_t)(b*NN + t0 + tk))*DD + h*DHD + fq);
    }

    for (int r = 0; r < NHASH; r++) {
        __syncthreads();   // qs ready / previous round done with rs
        for (int idx = tid; idx < 64*32; idx += 128) {
            int f = idx >> 5, iq = (idx & 31) * 4;
            *(float4*)&rs[f][iq] = *(const float4*)(rot + f*(NHASH*128) + r*128 + iq);
        }
        __syncthreads();

        ull acc2[4][4][2];   // [token tt][c][jpair], i = ig*4 + c*32 + jp*2+{0,1}
        #pragma unroll
        for (int tt = 0; tt < 4; tt++)
            #pragma unroll
            for (int c = 0; c < 4; c++) {
                acc2[tt][c][0] = 0ull; acc2[tt][c][1] = 0ull;
            }

        for (int f = 0; f < 64; f++) {
            ull qd[4];
            #pragma unroll
            for (int tt = 0; tt < 4; tt++) {
                float q = qs[quad*4 + tt][f];
                qd[tt] = pack2(q, q);
            }
            #pragma unroll
            for (int c = 0; c < 4; c++) {
                ulonglong2 rv = *(const ulonglong2*)&rs[f][ig*4 + c*32];
                #pragma unroll
                for (int tt = 0; tt < 4; tt++) {
                    fma2(acc2[tt][c][0], qd[tt], rv.x);
                    fma2(acc2[tt][c][1], qd[tt], rv.y);
                }
            }
        }

        #pragma unroll
        for (int tt = 0; tt < 4; tt++) {
            float bvv = -1e30f; int bi = 256;
            #pragma unroll
            for (int c = 0; c < 4; c++)
                #pragma unroll
                for (int jp = 0; jp < 2; jp++) {
                    float v0, v1;
                    unpack2(acc2[tt][c][jp], v0, v1);
                    float vv[2] = {v0, v1};
                    #pragma unroll
                    for (int u = 0; u < 2; u++) {
                        int i = ig*4 + c*32 + jp*2 + u;
                        float v = vv[u];
                        if (v > bvv || (v == bvv && i < bi)) { bvv = v; bi = i; }
                        float vn = -v; int i2 = 128 + i;
                        if (vn > bvv || (vn == bvv && i2 < bi)) { bvv = vn; bi = i2; }
                    }
                }
            #pragma unroll
            for (int m = 1; m < 8; m <<= 1) {
                float ov = __shfl_xor_sync(0xffffffffu, bvv, m);
                int   oi = __shfl_xor_sync(0xffffffffu, bi, m);
                if (ov > bvv || (ov == bvv && oi < bi)) { bvv = ov; bi = oi; }
            }
            if (ig == 0)
                g_bucket[(bh*NHASH + r)*NN + t0 + quad*4 + tt] = bi;
        }
    }
}

// ---------------- K3: stable counting sort per (bh, round) ------------------
// atomic place (unstable) + per-bucket insertion sort by token id = stable.
__global__ __launch_bounds__(256) void sort_kernel()
{
    __shared__ __align__(16) int bks[NN];
    __shared__ int tmp[NN];
    __shared__ int hist[NBUCK];
    __shared__ int offs[NBUCK];
    __shared__ int cnt[NBUCK];
    __shared__ int wsum[8];
    int bhr = blockIdx.x;              // bh*NHASH + r
    int tid = threadIdx.x;
    for (int t = tid; t < NN; t += 256) bks[t] = g_bucket[bhr*NN + t];
    hist[tid] = 0; cnt[tid] = 0;
    __syncthreads();
    for (int t = tid; t < NN; t += 256) atomicAdd(&hist[bks[t]], 1);
    __syncthreads();
    // parallel exclusive scan of hist (warp shuffle + 8-way carry)
    int hv = hist[tid];
    int incl = hv;
    #pragma unroll
    for (int d = 1; d < 32; d <<= 1) {
        int nv = __shfl_up_sync(0xffffffffu, incl, d);
        if ((tid & 31) >= d) incl += nv;
    }
    if ((tid & 31) == 31) wsum[tid >> 5] = incl;
    __syncthreads();
    if (tid == 0) {
        int s = 0;
        #pragma unroll
        for (int k = 0; k < 8; k++) { int t = wsum[k]; wsum[k] = s; s += t; }
    }
    __syncthreads();
    offs[tid] = incl - hv + wsum[tid >> 5];
    __syncthreads();
    // place (order arbitrary within bucket)
    for (int t = tid; t < NN; t += 256) {
        int b = bks[t];
        int p = atomicAdd(&cnt[b], 1);
        tmp[offs[b] + p] = t;
    }
    __syncthreads();
    // stabilize: sort each bucket's segment ascending by token id
    {
        int o = offs[tid], k = hist[tid];
        for (int x = 1; x < k; x++) {
            int key = tmp[o + x];
            int y = x - 1;
            while (y >= 0 && tmp[o + y] > key) { tmp[o + y + 1] = tmp[o + y]; y--; }
            tmp[o + y + 1] = key;
        }
    }
    __syncthreads();
    for (int t = tid; t < NN; t += 256) g_st[bhr*NN + t] = tmp[t];
}

// ---------------- K4: chunked attention, warp per chunk, FFMA2 --------------
// look_one_back runs over the FLAT 1024-chunk axis (crosses hash rounds).
__global__ __launch_bounds__(128) void attn_kernel()
{
    __shared__ __align__(16) float qs[4][4][68];
    __shared__ __align__(16) float ks[4][8][68];
    __shared__ __align__(16) float vs[4][8][68];
    __shared__ float ps[4][4][8];
    __shared__ int   tka[4][8];
    int w = threadIdx.x >> 5;
    int lane = threadIdx.x & 31;
    int C = blockIdx.x * 4 + w;                 // global (bh, flat chunk)
    int bh = C >> 10;
    int Cl = C & 1023;
    int r = Cl >> 8, c = Cl & 255;
    int Cp = (Cl + 1023) & 1023;                // previous chunk (wraps rounds)
    int rp = Cp >> 8, cp = Cp & 255;
    int b = bh >> 3, h = bh & 7;

    if (lane < 4) {
        tka[w][lane]     = g_st[(bh*NHASH + r)*NN + c*BSZ + lane];
        tka[w][lane + 4] = g_st[(bh*NHASH + rp)*NN + cp*BSZ + lane];
    }
    __syncwarp();

    // 8 qk rows + 8 v rows; q-rows (j<4) written raw AND normalized (k role)
    #pragma unroll
    for (int j = 0; j < 8; j++) {
        int t = tka[w][j];
        const float* ksrc = g_qk + ((size_t)(b*NN + t))*DD + h*DHD;
        const float* vsrc = g_v  + ((size_t)(b*NN + t))*DD + h*DHD;
        float k0 = ksrc[lane], k1 = ksrc[lane + 32];
        vs[w][j][lane]      = vsrc[lane];
        vs[w][j][lane + 32] = vsrc[lane + 32];
        if (j < 4) { qs[w][j][lane] = k0; qs[w][j][lane + 32] = k1; }
        float ss = k0*k0 + k1*k1;
        #pragma unroll
        for (int d = 16; d >= 1; d >>= 1) ss += __shfl_xor_sync(0xffffffffu, ss, d);
        float scale = 1.0f / fmaxf(sqrtf(ss), 1e-6f);   // make_unit_length
        ks[w][j][lane]      = k0 * scale;
        ks[w][j][lane + 32] = k1 * scale;
    }
    __syncwarp();

    int i = lane >> 3, j = lane & 7;            // 32 lanes = 4x8 dot products
    const ulonglong2* q2 = (const ulonglong2*)qs[w][i];
    const ulonglong2* k2 = (const ulonglong2*)ks[w][j];
    ull d2 = 0ull;
    #pragma unroll
    for (int fq = 0; fq < 16; fq++) {
        ulonglong2 a = q2[fq], kk = k2[fq];
        fma2(d2, a.x, kk.x);
        fma2(d2, a.y, kk.y);
    }
    float dlo, dhi;
    unpack2(d2, dlo, dhi);
    float d = (dlo + dhi) * 0.125f;              // dh^-0.5
    if (tka[w][i] == tka[w][j]) d = -5e4f;       // self-token mask (by id!)

    float m = d;
    #pragma unroll
    for (int dd = 4; dd >= 1; dd >>= 1) m = fmaxf(m, __shfl_xor_sync(0xffffffffu, m, dd));
    float e = expf(d - m);
    float s = e;
    #pragma unroll
    for (int dd = 4; dd >= 1; dd >>= 1) s += __shfl_xor_sync(0xffffffffu, s, dd);
    float lse = m + logf(s);
    ps[w][i][j] = e / s;
    __syncwarp();

    // output: 4 rows x 32 f-pairs; per it all lanes share oi = it
    #pragma unroll
    for (int it = 0; it < 4; it++) {
        int oi = it, fp = lane;
        ull acc = 0ull;
        #pragma unroll
        for (int jj = 0; jj < 8; jj++) {
            float p = ps[w][oi][jj];
            ull pd = pack2(p, p);
            ull vv = *(const ull*)&vs[w][jj][fp*2];
            fma2(acc, pd, vv);
        }
        *(ull*)&g_o[(((size_t)(bh*NHASH + r))*NN + tka[w][oi])*DHD + fp*2] = acc;
    }
    if (j == 0)
        g_logits[(bh*NHASH + r)*NN + tka[w][i]] = lse;
}

// ---------------- K5: combine hash rounds + merge heads (FFMA2) -------------
__global__ __launch_bounds__(256) void combine_kernel()
{
    int bh = blockIdx.y;
    int t = blockIdx.x * 8 + (threadIdx.x >> 5);
    int fp = threadIdx.x & 31;
    int b = bh >> 3, h = bh & 7;
    float l[NHASH];
    #pragma unroll
    for (int r = 0; r < NHASH; r++) l[r] = g_logits[(bh*NHASH + r)*NN + t];
    float m = fmaxf(fmaxf(l[0], l[1]), fmaxf(l[2], l[3]));
    float s = 0.f;
    #pragma unroll
    for (int r = 0; r < NHASH; r++) s += expf(l[r] - m);
    ull acc = 0ull;
    #pragma unroll
    for (int r = 0; r < NHASH; r++) {
        float wr = expf(l[r] - m) / s;
        ull wd = pack2(wr, wr);
        ull vv = *(const ull*)&g_o[(((size_t)(bh*NHASH + r))*NN + t)*DHD + fp*2];
        fma2(acc, wd, vv);
    }
    *(ull*)&g_att[((size_t)(b*NN + t))*DD + h*DHD + fp*2] = acc;
}

// ---------------- launch ----------------------------------------------------
extern "C" void kernel_launch(void* const* d_in, const int* in_sizes, int n_in,
                              void* d_out, int out_size)
{
    (void)in_sizes; (void)n_in; (void)out_size;
    const float* queries = (const float*)d_in[0];
    // d_in[1] keys, d_in[2] values, d_in[8] attn_mask: unused by ReformerLayer
    const float* Wqk  = (const float*)d_in[3];
    const float* Wv   = (const float*)d_in[4];
    const float* Wout = (const float*)d_in[5];
    const float* bout = (const float*)d_in[6];
    const float* rot  = (const float*)d_in[7];
    float* out = (float*)d_out;

    float *qk, *v, *att;
    cudaGetSymbolAddress((void**)&qk,  g_qk);
    cudaGetSymbolAddress((void**)&v,   g_v);
    cudaGetSymbolAddress((void**)&att, g_att);

    // qk- and v-GEMM fused into one launch via grid.z
    dim3 gdual(DD/128, MTOT/128, 2);   // (4, 64, 2) = 512 blocks
    sgemm128<false><<<gdual, 256>>>(queries, Wqk, Wv, nullptr, qk, v, MTOT, DD, DD);
    hash_kernel<<<dim3(NN/64, BHN), 128>>>(rot);
    sort_kernel<<<BHN*NHASH, 256>>>();
    attn_kernel<<<(BHN*CHTOT)/4, 128>>>();
    combine_kernel<<<dim3(NN/8, BHN), 256>>>();
    dim3 gout(DD/128, MTOT/128, 1);
    sgemm128<true><<<gout, 256>>>(att, Wout, Wout, bout, out, out, MTOT, DD, DD);
}

// round 8
// speedup vs baseline: 1.0864x; 1.0864x over previous
#include <cuda_runtime.h>
#include <math.h>

// ---------------- problem constants ----------------
#define BN     8      // batch
#define NN     1024   // seq len
#define DD     512    // model dim
#define HH     8      // heads
#define DHD    64     // dim per head
#define NHASH  4      // hash rounds
#define NBUCK  256    // buckets per round (N / BUCKET)
#define BSZ    4      // bucket size
#define BHN    (BN*HH)        // 64
#define MTOT   (BN*NN)        // 8192 rows for GEMMs
#define CHTOT  (NHASH*NBUCK)  // 1024 chunks per bh (flat, cross-round)

typedef unsigned long long ull;

// ---- packed f32x2 helpers (FFMA2 path; bit-exact fp32, 2 lanes/instr) ------
__device__ __forceinline__ ull pack2(float lo, float hi) {
    ull r; asm("mov.b64 %0, {%1, %2};" : "=l"(r) : "f"(lo), "f"(hi)); return r;
}
__device__ __forceinline__ void unpack2(ull v, float& lo, float& hi) {
    asm("mov.b64 {%0, %1}, %2;" : "=f"(lo), "=f"(hi) : "l"(v));
}
__device__ __forceinline__ void fma2(ull& d, ull a, ull b) {
    asm("fma.rn.f32x2 %0, %1, %2, %0;" : "+l"(d) : "l"(a), "l"(b));
}

// ---------------- scratch (device globals; no runtime alloc) ----------------
__device__ float g_qk    [BN*NN*DD];          // 16 MB
__device__ float g_v     [BN*NN*DD];          // 16 MB
__device__ int   g_bucket[BHN*NHASH*NN];      // 1 MB
__device__ int   g_st    [BHN*NHASH*NN];      // 1 MB
__device__ float g_o     [(size_t)BHN*NHASH*NN*DHD]; // 64 MB
__device__ float g_logits[BHN*NHASH*NN];      // 1 MB
__device__ float g_att   [BN*NN*DD];          // 16 MB

// ---------------- K1/K6: SGEMM 128x128 tile, BK=8, double-buffered, FFMA2 ---
// (exact R6 version — measured 112us/GEMM)
template<bool HASBIAS>
__global__ __launch_bounds__(256, 2) void sgemm128(
    const float* __restrict__ A, const float* __restrict__ Bm,
    const float* __restrict__ bias, float* __restrict__ C,
    int M, int Nn, int K)
{
    __shared__ __align__(16) float As[2][8][132];
    __shared__ __align__(16) float Bs[2][8][132];
    int tid = threadIdx.x;
    int bm = blockIdx.y * 128, bn = blockIdx.x * 128;
    int ty = tid >> 4, tx = tid & 15;

    int arow = tid >> 1;            // 0..127
    int akq  = (tid & 1) * 4;       // 0 or 4
    int bk   = tid >> 5;            // 0..7
    int bnq  = (tid & 31) * 4;      // 0..124

    const float* Aptr = A  + (size_t)(bm + arow) * K + akq;
    const float* Bptr = Bm + (size_t)bk * Nn + bn + bnq;

    ull acc[8][4];
    #pragma unroll
    for (int i = 0; i < 8; i++)
        #pragma unroll
        for (int jp = 0; jp < 4; jp++) acc[i][jp] = 0ull;

    float4 av = *(const float4*)(Aptr);
    float4 bv = *(const float4*)(Bptr);
    As[0][akq+0][arow] = av.x;
    As[0][akq+1][arow] = av.y;
    As[0][akq+2][arow] = av.z;
    As[0][akq+3][arow] = av.w;
    *(float4*)&Bs[0][bk][bnq] = bv;
    __syncthreads();

    int buf = 0;
    for (int k0 = 8; k0 <= K; k0 += 8) {
        if (k0 < K) {
            av = *(const float4*)(Aptr + k0);
            bv = *(const float4*)(Bptr + (size_t)k0 * Nn);
        }
        #pragma unroll
        for (int k = 0; k < 8; k++) {
            float4 a0 = *(const float4*)&As[buf][k][ty*4];
            float4 a1 = *(const float4*)&As[buf][k][64 + ty*4];
            ulonglong2 b0 = *(const ulonglong2*)&Bs[buf][k][tx*4];
            ulonglong2 b1 = *(const ulonglong2*)&Bs[buf][k][64 + tx*4];
            ull ad[8];
            ad[0] = pack2(a0.x, a0.x); ad[1] = pack2(a0.y, a0.y);
            ad[2] = pack2(a0.z, a0.z); ad[3] = pack2(a0.w, a0.w);
            ad[4] = pack2(a1.x, a1.x); ad[5] = pack2(a1.y, a1.y);
            ad[6] = pack2(a1.z, a1.z); ad[7] = pack2(a1.w, a1.w);
            #pragma unroll
            for (int i = 0; i < 8; i++) {
                fma2(acc[i][0], ad[i], b0.x);
                fma2(acc[i][1], ad[i], b0.y);
                fma2(acc[i][2], ad[i], b1.x);
                fma2(acc[i][3], ad[i], b1.y);
            }
        }
        if (k0 < K) {
            buf ^= 1;
            As[buf][akq+0][arow] = av.x;
            As[buf][akq+1][arow] = av.y;
            As[buf][akq+2][arow] = av.z;
            As[buf][akq+3][arow] = av.w;
            *(float4*)&Bs[buf][bk][bnq] = bv;
            __syncthreads();
        }
    }

    #pragma unroll
    for (int rh = 0; rh < 2; rh++)
        #pragma unroll
        for (int i = 0; i < 4; i++) {
            int row = bm + rh*64 + ty*4 + i;
            #pragma unroll
            for (int ch = 0; ch < 2; ch++) {
                float4 o;
                unpack2(acc[rh*4+i][ch*2+0], o.x, o.y);
                unpack2(acc[rh*4+i][ch*2+1], o.z, o.w);
                int col = bn + ch*64 + tx*4;
                if (HASBIAS) {
                    o.x += bias[col+0]; o.y += bias[col+1];
                    o.z += bias[col+2]; o.w += bias[col+3];
                }
                *(float4*)(C + (size_t)row * Nn + col) = o;
            }
        }
}

// ---------------- K2: LSH hashing, FFMA2, 4 tok x 16 i per thread -----------
// Per-j accumulation chains identical to scalar version -> buckets bitwise same.
__global__ __launch_bounds__(128) void hash_kernel(const float* __restrict__ rot)
{
    __shared__ __align__(16) float qs[64][64];    // 16 KB
    __shared__ __align__(16) float rs[64][128];   // 32 KB
    int bh = blockIdx.y;
    int t0 = blockIdx.x * 64;
    int b = bh >> 3, h = bh & 7;
    int tid = threadIdx.x;
    int quad = tid >> 3, ig = tid & 7;

    for (int idx = tid; idx < 64*16; idx += 128) {
        int tk = idx >> 4, fq = (idx & 15) * 4;
        *(float4*)&qs[tk][fq] =
            *(const float4*)(g_qk + ((size_t)(b*NN + t0 + tk))*DD + h*DHD + fq);
    }

    for (int r = 0; r < NHASH; r++) {
        __syncthreads();   // qs ready / previous round done with rs
        for (int idx = tid; idx < 64*32; idx += 128) {
            int f = idx >> 5, iq = (idx & 31) * 4;
            *(float4*)&rs[f][iq] = *(const float4*)(rot + f*(NHASH*128) + r*128 + iq);
        }
        __syncthreads();

        ull acc2[4][4][2];   // [token tt][c][jpair], i = ig*4 + c*32 + jp*2+{0,1}
        #pragma unroll
        for (int tt = 0; tt < 4; tt++)
            #pragma unroll
            for (int c = 0; c < 4; c++) {
                acc2[tt][c][0] = 0ull; acc2[tt][c][1] = 0ull;
            }

        for (int f = 0; f < 64; f++) {
            ull qd[4];
            #pragma unroll
            for (int tt = 0; tt < 4; tt++) {
                float q = qs[quad*4 + tt][f];
                qd[tt] = pack2(q, q);
            }
            #pragma unroll
            for (int c = 0; c < 4; c++) {
                ulonglong2 rv = *(const ulonglong2*)&rs[f][ig*4 + c*32];
                #pragma unroll
                for (int tt = 0; tt < 4; tt++) {
                    fma2(acc2[tt][c][0], qd[tt], rv.x);
                    fma2(acc2[tt][c][1], qd[tt], rv.y);
                }
            }
        }

        #pragma unroll
        for (int tt = 0; tt < 4; tt++) {
            float bvv = -1e30f; int bi = 256;
            #pragma unroll
            for (int c = 0; c < 4; c++)
                #pragma unroll
                for (int jp = 0; jp < 2; jp++) {
                    float v0, v1;
                    unpack2(acc2[tt][c][jp], v0, v1);
                    float vv[2] = {v0, v1};
                    #pragma unroll
                    for (int u = 0; u < 2; u++) {
                        int i = ig*4 + c*32 + jp*2 + u;
                        float v = vv[u];
                        if (v > bvv || (v == bvv && i < bi)) { bvv = v; bi = i; }
                        float vn = -v; int i2 = 128 + i;
                        if (vn > bvv || (vn == bvv && i2 < bi)) { bvv = vn; bi = i2; }
                    }
                }
            #pragma unroll
            for (int m = 1; m < 8; m <<= 1) {
                float ov = __shfl_xor_sync(0xffffffffu, bvv, m);
                int   oi = __shfl_xor_sync(0xffffffffu, bi, m);
                if (ov > bvv || (ov == bvv && oi < bi)) { bvv = ov; bi = oi; }
            }
            if (ig == 0)
                g_bucket[(bh*NHASH + r)*NN + t0 + quad*4 + tt] = bi;
        }
    }
}

// ---------------- K3: stable counting sort per (bh, round) ------------------
// atomic place (unstable) + per-bucket insertion sort by token id = stable.
__global__ __launch_bounds__(256) void sort_kernel()
{
    __shared__ __align__(16) int bks[NN];
    __shared__ int tmp[NN];
    __shared__ int hist[NBUCK];
    __shared__ int offs[NBUCK];
    __shared__ int cnt[NBUCK];
    __shared__ int wsum[8];
    int bhr = blockIdx.x;              // bh*NHASH + r
    int tid = threadIdx.x;
    for (int t = tid; t < NN; t += 256) bks[t] = g_bucket[bhr*NN + t];
    hist[tid] = 0; cnt[tid] = 0;
    __syncthreads();
    for (int t = tid; t < NN; t += 256) atomicAdd(&hist[bks[t]], 1);
    __syncthreads();
    // parallel exclusive scan of hist (warp shuffle + 8-way carry)
    int hv = hist[tid];
    int incl = hv;
    #pragma unroll
    for (int d = 1; d < 32; d <<= 1) {
        int nv = __shfl_up_sync(0xffffffffu, incl, d);
        if ((tid & 31) >= d) incl += nv;
    }
    if ((tid & 31) == 31) wsum[tid >> 5] = incl;
    __syncthreads();
    if (tid == 0) {
        int s = 0;
        #pragma unroll
        for (int k = 0; k < 8; k++) { int t = wsum[k]; wsum[k] = s; s += t; }
    }
    __syncthreads();
    offs[tid] = incl - hv + wsum[tid >> 5];
    __syncthreads();
    // place (order arbitrary within bucket)
    for (int t = tid; t < NN; t += 256) {
        int b = bks[t];
        int p = atomicAdd(&cnt[b], 1);
        tmp[offs[b] + p] = t;
    }
    __syncthreads();
    // stabilize: sort each bucket's segment ascending by token id
    {
        int o = offs[tid], k = hist[tid];
        for (int x = 1; x < k; x++) {
            int key = tmp[o + x];
            int y = x - 1;
            while (y >= 0 && tmp[o + y] > key) { tmp[o + y + 1] = tmp[o + y]; y--; }
            tmp[o + y + 1] = key;
        }
    }
    __syncthreads();
    for (int t = tid; t < NN; t += 256) g_st[bhr*NN + t] = tmp[t];
}

// ---------------- K4: chunked attention, warp per chunk ---------------------
// Lane-pair layout: lane holds features (2L, 2L+1). v stays in registers;
// probabilities broadcast via shuffle. look_one_back over FLAT chunk axis.
__global__ __launch_bounds__(128) void attn_kernel()
{
    __shared__ __align__(16) float qs[4][4][68];
    __shared__ __align__(16) float ks[4][8][68];
    __shared__ int   tka[4][8];
    int w = threadIdx.x >> 5;
    int lane = threadIdx.x & 31;
    int C = blockIdx.x * 4 + w;                 // global (bh, flat chunk)
    int bh = C >> 10;
    int Cl = C & 1023;
    int r = Cl >> 8, c = Cl & 255;
    int Cp = (Cl + 1023) & 1023;                // previous chunk (wraps rounds)
    int rp = Cp >> 8, cp = Cp & 255;
    int b = bh >> 3, h = bh & 7;

    if (lane < 4) {
        tka[w][lane]     = g_st[(bh*NHASH + r)*NN + c*BSZ + lane];
        tka[w][lane + 4] = g_st[(bh*NHASH + rp)*NN + cp*BSZ + lane];
    }
    __syncwarp();

    // Load 8 qk rows + 8 v rows as float2 pairs; v kept in registers only.
    ull v2[8];
    #pragma unroll
    for (int j = 0; j < 8; j++) {
        int t = tka[w][j];
        const float* ksrc = g_qk + ((size_t)(b*NN + t))*DD + h*DHD;
        const float* vsrc = g_v  + ((size_t)(b*NN + t))*DD + h*DHD;
        float2 kp = *(const float2*)(ksrc + 2*lane);
        float2 vp = *(const float2*)(vsrc + 2*lane);
        v2[j] = pack2(vp.x, vp.y);
        if (j < 4) *(float2*)&qs[w][j][2*lane] = kp;   // raw q role
        float ss = kp.x*kp.x + kp.y*kp.y;
        #pragma unroll
        for (int d = 16; d >= 1; d >>= 1) ss += __shfl_xor_sync(0xffffffffu, ss, d);
        float scale = 1.0f / fmaxf(sqrtf(ss), 1e-6f);   // make_unit_length
        float2 kn; kn.x = kp.x * scale; kn.y = kp.y * scale;
        *(float2*)&ks[w][j][2*lane] = kn;
    }
    __syncwarp();

    int i = lane >> 3, j = lane & 7;            // 32 lanes = 4x8 dot products
    const ulonglong2* q2 = (const ulonglong2*)qs[w][i];
    const ulonglong2* k2 = (const ulonglong2*)ks[w][j];
    ull d2 = 0ull;
    #pragma unroll
    for (int fq = 0; fq < 16; fq++) {
        ulonglong2 a = q2[fq], kk = k2[fq];
        fma2(d2, a.x, kk.x);
        fma2(d2, a.y, kk.y);
    }
    float dlo, dhi;
    unpack2(d2, dlo, dhi);
    float d = (dlo + dhi) * 0.125f;              // dh^-0.5
    if (tka[w][i] == tka[w][j]) d = -5e4f;       // self-token mask (by id!)

    float m = d;
    #pragma unroll
    for (int dd = 4; dd >= 1; dd >>= 1) m = fmaxf(m, __shfl_xor_sync(0xffffffffu, m, dd));
    float e = expf(d - m);
    float s = e;
    #pragma unroll
    for (int dd = 4; dd >= 1; dd >>= 1) s += __shfl_xor_sync(0xffffffffu, s, dd);
    float lse = m + logf(s);
    float pval = e / s;                          // prob for (i, j), lives in lane i*8+j

    // output: 4 rows; lane handles feature pair (2L, 2L+1); p via shuffle
    #pragma unroll
    for (int it = 0; it < 4; it++) {
        ull acc = 0ull;
        #pragma unroll
        for (int jj = 0; jj < 8; jj++) {
            float p = __shfl_sync(0xffffffffu, pval, it*8 + jj);
            fma2(acc, pack2(p, p), v2[jj]);
        }
        *(ull*)&g_o[(((size_t)(bh*NHASH + r))*NN + tka[w][it])*DHD + 2*lane] = acc;
    }
    if (j == 0)
        g_logits[(bh*NHASH + r)*NN + tka[w][i]] = lse;
}

// ---------------- K5: combine hash rounds + merge heads (FFMA2) -------------
__global__ __launch_bounds__(256) void combine_kernel()
{
    int bh = blockIdx.y;
    int t = blockIdx.x * 8 + (threadIdx.x >> 5);
    int fp = threadIdx.x & 31;
    int b = bh >> 3, h = bh & 7;
    float l[NHASH];
    #pragma unroll
    for (int r = 0; r < NHASH; r++) l[r] = g_logits[(bh*NHASH + r)*NN + t];
    float m = fmaxf(fmaxf(l[0], l[1]), fmaxf(l[2], l[3]));
    float s = 0.f;
    #pragma unroll
    for (int r = 0; r < NHASH; r++) s += expf(l[r] - m);
    ull acc = 0ull;
    #pragma unroll
    for (int r = 0; r < NHASH; r++) {
        float wr = expf(l[r] - m) / s;
        ull wd = pack2(wr, wr);
        ull vv = *(const ull*)&g_o[(((size_t)(bh*NHASH + r))*NN + t)*DHD + fp*2];
        fma2(acc, wd, vv);
    }
    *(ull*)&g_att[((size_t)(b*NN + t))*DD + h*DHD + fp*2] = acc;
}

// ---------------- launch ----------------------------------------------------
extern "C" void kernel_launch(void* const* d_in, const int* in_sizes, int n_in,
                              void* d_out, int out_size)
{
    (void)in_sizes; (void)n_in; (void)out_size;
    const float* queries = (const float*)d_in[0];
    // d_in[1] keys, d_in[2] values, d_in[8] attn_mask: unused by ReformerLayer
    const float* Wqk  = (const float*)d_in[3];
    const float* Wv   = (const float*)d_in[4];
    const float* Wout = (const float*)d_in[5];
    const float* bout = (const float*)d_in[6];
    const float* rot  = (const float*)d_in[7];
    float* out = (float*)d_out;

    float *qk, *v, *att;
    cudaGetSymbolAddress((void**)&qk,  g_qk);
    cudaGetSymbolAddress((void**)&v,   g_v);
    cudaGetSymbolAddress((void**)&att, g_att);

    dim3 ggrid(DD/128, MTOT/128);   // (4, 64) = 256 blocks
    sgemm128<false><<<ggrid, 256>>>(queries, Wqk, nullptr, qk, MTOT, DD, DD);
    hash_kernel<<<dim3(NN/64, BHN), 128>>>(rot);
    sort_kernel<<<BHN*NHASH, 256>>>();
    sgemm128<false><<<ggrid, 256>>>(queries, Wv,  nullptr, v,  MTOT, DD, DD);
    attn_kernel<<<(BHN*CHTOT)/4, 128>>>();
    combine_kernel<<<dim3(NN/8, BHN), 256>>>();
    sgemm128<true><<<ggrid, 256>>>(att, Wout, bout, out, MTOT, DD, DD);
}

// round 10
// speedup vs baseline: 1.1110x; 1.0227x over previous
#include <cuda_runtime.h>
#include <math.h>

// ---------------- problem constants ----------------
#define BN     8
#define NN     1024
#define DD     512
#define HH     8
#define DHD    64
#define NHASH  4
#define NBUCK  256
#define BSZ    4
#define BHN    (BN*HH)
#define MTOT   (BN*NN)
#define CHTOT  (NHASH*NBUCK)

typedef unsigned long long ull;

// ---- packed f32x2 helpers (FFMA2; bit-exact fp32, 2 lanes/instr) -----------
__device__ __forceinline__ ull pack2(float lo, float hi) {
    ull r; asm("mov.b64 %0, {%1, %2};" : "=l"(r) : "f"(lo), "f"(hi)); return r;
}
__device__ __forceinline__ void unpack2(ull v, float& lo, float& hi) {
    asm("mov.b64 {%0, %1}, %2;" : "=f"(lo), "=f"(hi) : "l"(v));
}
__device__ __forceinline__ void fma2(ull& d, ull a, ull b) {
    asm("fma.rn.f32x2 %0, %1, %2, %0;" : "+l"(d) : "l"(a), "l"(b));
}

// ---- 3xTF32 helpers --------------------------------------------------------
__device__ __forceinline__ void tf32_split(float x, unsigned& hi, unsigned& lo) {
    unsigned h; asm("cvt.rna.tf32.f32 %0, %1;" : "=r"(h) : "f"(x));
    float r = x - __uint_as_float(h);
    unsigned l; asm("cvt.rna.tf32.f32 %0, %1;" : "=r"(l) : "f"(r));
    hi = h; lo = l;
}
__device__ __forceinline__ void mma_tf32(float* c, const unsigned* a, const unsigned* b) {
    asm volatile("mma.sync.aligned.m16n8k8.row.col.f32.tf32.tf32.f32 "
        "{%0,%1,%2,%3}, {%4,%5,%6,%7}, {%8,%9}, {%0,%1,%2,%3};"
        : "+f"(c[0]), "+f"(c[1]), "+f"(c[2]), "+f"(c[3])
        : "r"(a[0]), "r"(a[1]), "r"(a[2]), "r"(a[3]), "r"(b[0]), "r"(b[1]));
}

// ---------------- scratch ---------------------------------------------------
__device__ float g_qk    [BN*NN*DD];
__device__ float g_v     [BN*NN*DD];
__device__ int   g_bucket[BHN*NHASH*NN];
__device__ int   g_st    [BHN*NHASH*NN];
__device__ float g_o     [(size_t)BHN*NHASH*NN*DHD];
__device__ float g_logits[BHN*NHASH*NN];
__device__ float g_att   [BN*NN*DD];

// ---------------- K1 (qk): SGEMM 128x128, BK=8, FFMA2 (exact R6/R8 version) -
template<bool HASBIAS>
__global__ __launch_bounds__(256, 2) void sgemm128(
    const float* __restrict__ A, const float* __restrict__ Bm,
    const float* __restrict__ bias, float* __restrict__ C,
    int M, int Nn, int K)
{
    __shared__ __align__(16) float As[2][8][132];
    __shared__ __align__(16) float Bs[2][8][132];
    int tid = threadIdx.x;
    int bm = blockIdx.y * 128, bn = blockIdx.x * 128;
    int ty = tid >> 4, tx = tid & 15;

    int arow = tid >> 1;
    int akq  = (tid & 1) * 4;
    int bk   = tid >> 5;
    int bnq  = (tid & 31) * 4;

    const float* Aptr = A  + (size_t)(bm + arow) * K + akq;
    const float* Bptr = Bm + (size_t)bk * Nn + bn + bnq;

    ull acc[8][4];
    #pragma unroll
    for (int i = 0; i < 8; i++)
        #pragma unroll
        for (int jp = 0; jp < 4; jp++) acc[i][jp] = 0ull;

    float4 av = *(const float4*)(Aptr);
    float4 bv = *(const float4*)(Bptr);
    As[0][akq+0][arow] = av.x;
    As[0][akq+1][arow] = av.y;
    As[0][akq+2][arow] = av.z;
    As[0][akq+3][arow] = av.w;
    *(float4*)&Bs[0][bk][bnq] = bv;
    __syncthreads();

    int buf = 0;
    for (int k0 = 8; k0 <= K; k0 += 8) {
        if (k0 < K) {
            av = *(const float4*)(Aptr + k0);
            bv = *(const float4*)(Bptr + (size_t)k0 * Nn);
        }
        #pragma unroll
        for (int k = 0; k < 8; k++) {
            float4 a0 = *(const float4*)&As[buf][k][ty*4];
            float4 a1 = *(const float4*)&As[buf][k][64 + ty*4];
            ulonglong2 b0 = *(const ulonglong2*)&Bs[buf][k][tx*4];
            ulonglong2 b1 = *(const ulonglong2*)&Bs[buf][k][64 + tx*4];
            ull ad[8];
            ad[0] = pack2(a0.x, a0.x); ad[1] = pack2(a0.y, a0.y);
            ad[2] = pack2(a0.z, a0.z); ad[3] = pack2(a0.w, a0.w);
            ad[4] = pack2(a1.x, a1.x); ad[5] = pack2(a1.y, a1.y);
            ad[6] = pack2(a1.z, a1.z); ad[7] = pack2(a1.w, a1.w);
            #pragma unroll
            for (int i = 0; i < 8; i++) {
                fma2(acc[i][0], ad[i], b0.x);
                fma2(acc[i][1], ad[i], b0.y);
                fma2(acc[i][2], ad[i], b1.x);
                fma2(acc[i][3], ad[i], b1.y);
            }
        }
        if (k0 < K) {
            buf ^= 1;
            As[buf][akq+0][arow] = av.x;
            As[buf][akq+1][arow] = av.y;
            As[buf][akq+2][arow] = av.z;
            As[buf][akq+3][arow] = av.w;
            *(float4*)&Bs[buf][bk][bnq] = bv;
            __syncthreads();
        }
    }

    #pragma unroll
    for (int rh = 0; rh < 2; rh++)
        #pragma unroll
        for (int i = 0; i < 4; i++) {
            int row = bm + rh*64 + ty*4 + i;
            #pragma unroll
            for (int ch = 0; ch < 2; ch++) {
                float4 o;
                unpack2(acc[rh*4+i][ch*2+0], o.x, o.y);
                unpack2(acc[rh*4+i][ch*2+1], o.z, o.w);
                int col = bn + ch*64 + tx*4;
                if (HASBIAS) {
                    o.x += bias[col+0]; o.y += bias[col+1];
                    o.z += bias[col+2]; o.w += bias[col+3];
                }
                *(float4*)(C + (size_t)row * Nn + col) = o;
            }
        }
}

// ---------------- K1b (v, out): 3xTF32 tensor-core GEMM ---------------------
// Block 128x128, 256 thr (8 warps, 2x4), warp tile 64x32, BK=16.
// A/B split into tf32 (hi, lo); D = Al*Bb + Ab*Bl + Ab*Bb (fp32 accum).
// smem rows k-pair-permuted: within a k8 group, pos(k) = 2*(k&3) + (k>>2),
// so a fragment's (k, k+4) pair is one LDS.64.
template<bool HASBIAS>
__global__ __launch_bounds__(256, 2) void gemm_tc(
    const float* __restrict__ A, const float* __restrict__ Bm,
    const float* __restrict__ bias, float* __restrict__ C,
    int M, int Nn, int K)
{
    __shared__ unsigned Abh[128][18], Abl[128][18];
    __shared__ unsigned Bbh[128][18], Bbl[128][18];
    int tid = threadIdx.x;
    int bm = blockIdx.y * 128, bn = blockIdx.x * 128;
    int wid = tid >> 5, lane = tid & 31;
    int m0 = (wid >> 2) * 64, n0 = (wid & 3) * 32;
    int grp = lane >> 2, cc = lane & 3;

    float acc[4][4][4];
    #pragma unroll
    for (int t = 0; t < 4; t++)
        #pragma unroll
        for (int u = 0; u < 4; u++)
            #pragma unroll
            for (int x = 0; x < 4; x++) acc[t][u][x] = 0.f;

    int bn_n = tid & 127, bkh = tid >> 7;   // B staging: own one n-row, 8 k's

    for (int k0 = 0; k0 < K; k0 += 16) {
        __syncthreads();
        // stage A: 2 float4/thread, scatter stride-2 into own row
        #pragma unroll
        for (int l = 0; l < 2; l++) {
            int e = tid + l * 256;
            int r = e >> 2, kq = (e & 3) * 4;
            float4 v = *(const float4*)(A + (size_t)(bm + r) * K + k0 + kq);
            int pb = ((kq >> 3) << 3) + ((kq >> 2) & 1);
            unsigned h, lo;
            tf32_split(v.x, h, lo); Abh[r][pb+0] = h; Abl[r][pb+0] = lo;
            tf32_split(v.y, h, lo); Abh[r][pb+2] = h; Abl[r][pb+2] = lo;
            tf32_split(v.z, h, lo); Abh[r][pb+4] = h; Abl[r][pb+4] = lo;
            tf32_split(v.w, h, lo); Abh[r][pb+6] = h; Abl[r][pb+6] = lo;
        }
        // stage B (transpose W[k][n] -> Bs[n][perm(k)]): own row, 4 STS.64 x2
        {
            unsigned hb[8], lb[8];
            #pragma unroll
            for (int j = 0; j < 8; j++) {
                float v = Bm[(size_t)(k0 + bkh*8 + j) * Nn + bn + bn_n];
                int pl = (j < 4) ? 2*j : 2*(j-4) + 1;
                tf32_split(v, hb[pl], lb[pl]);
            }
            #pragma unroll
            for (int s = 0; s < 4; s++) {
                *(uint2*)&Bbh[bn_n][bkh*8 + 2*s] = make_uint2(hb[2*s], hb[2*s+1]);
                *(uint2*)&Bbl[bn_n][bkh*8 + 2*s] = make_uint2(lb[2*s], lb[2*s+1]);
            }
        }
        __syncthreads();
        #pragma unroll
        for (int g = 0; g < 2; g++) {
            uint2 bfh[4], bfl[4];
            #pragma unroll
            for (int u = 0; u < 4; u++) {
                int nr = n0 + u*8 + grp;
                bfh[u] = *(const uint2*)&Bbh[nr][g*8 + 2*cc];
                bfl[u] = *(const uint2*)&Bbl[nr][g*8 + 2*cc];
            }
            #pragma unroll
            for (int t = 0; t < 4; t++) {
                int r0 = m0 + t*16 + grp;
                uint2 uh0 = *(const uint2*)&Abh[r0  ][g*8 + 2*cc];
                uint2 uh1 = *(const uint2*)&Abh[r0+8][g*8 + 2*cc];
                uint2 ul0 = *(const uint2*)&Abl[r0  ][g*8 + 2*cc];
                uint2 ul1 = *(const uint2*)&Abl[r0+8][g*8 + 2*cc];
                unsigned afh[4] = {uh0.x, uh1.x, uh0.y, uh1.y};
                unsigned afl[4] = {ul0.x, ul1.x, ul0.y, ul1.y};
                #pragma unroll
                for (int u = 0; u < 4; u++) {
                    unsigned bh2[2] = {bfh[u].x, bfh[u].y};
                    unsigned bl2[2] = {bfl[u].x, bfl[u].y};
                    mma_tf32(acc[t][u], afl, bh2);   // Al*Bb
                    mma_tf32(acc[t][u], afh, bl2);   // Ab*Bl
                    mma_tf32(acc[t][u], afh, bh2);   // Ab*Bb
                }
            }
        }
    }
    // epilogue
    #pragma unroll
    for (int t = 0; t < 4; t++)
        #pragma unroll
        for (int u = 0; u < 4; u++) {
            int row = bm + m0 + t*16 + grp;
            int col = bn + n0 + u*8 + 2*cc;
            float2 o0 = make_float2(acc[t][u][0], acc[t][u][1]);
            float2 o1 = make_float2(acc[t][u][2], acc[t][u][3]);
            if (HASBIAS) {
                float2 bv = *(const float2*)(bias + col);
                o0.x += bv.x; o0.y += bv.y; o1.x += bv.x; o1.y += bv.y;
            }
            *(float2*)(C + (size_t)row * Nn + col)     = o0;
            *(float2*)(C + (size_t)(row+8) * Nn + col) = o1;
        }
}

// ---------------- K2: LSH hashing, FFMA2 (bitwise-stable buckets) -----------
__global__ __launch_bounds__(128) void hash_kernel(const float* __restrict__ rot)
{
    __shared__ __align__(16) float qs[64][64];
    __shared__ __align__(16) float rs[64][128];
    int bh = blockIdx.y;
    int t0 = blockIdx.x * 64;
    int b = bh >> 3, h = bh & 7;
    int tid = threadIdx.x;
    int quad = tid >> 3, ig = tid & 7;

    for (int idx = tid; idx < 64*16; idx += 128) {
        int tk = idx >> 4, fq = (idx & 15) * 4;
        *(float4*)&qs[tk][fq] =
            *(const float4*)(g_qk + ((size_t)(b*NN + t0 + tk))*DD + h*DHD + fq);
    }

    for (int r = 0; r < NHASH; r++) {
        __syncthreads();
        for (int idx = tid; idx < 64*32; idx += 128) {
            int f = idx >> 5, iq = (idx & 31) * 4;
            *(float4*)&rs[f][iq] = *(const float4*)(rot + f*(NHASH*128) + r*128 + iq);
        }
        __syncthreads();

        ull acc2[4][4][2];
        #pragma unroll
        for (int tt = 0; tt < 4; tt++)
            #pragma unroll
            for (int c = 0; c < 4; c++) {
                acc2[tt][c][0] = 0ull; acc2[tt][c][1] = 0ull;
            }

        for (int f = 0; f < 64; f++) {
            ull qd[4];
            #pragma unroll
            for (int tt = 0; tt < 4; tt++) {
                float q = qs[quad*4 + tt][f];
                qd[tt] = pack2(q, q);
            }
            #pragma unroll
            for (int c = 0; c < 4; c++) {
                ulonglong2 rv = *(const ulonglong2*)&rs[f][ig*4 + c*32];
                #pragma unroll
                for (int tt = 0; tt < 4; tt++) {
                    fma2(acc2[tt][c][0], qd[tt], rv.x);
                    fma2(acc2[tt][c][1], qd[tt], rv.y);
                }
            }
        }

        #pragma unroll
        for (int tt = 0; tt < 4; tt++) {
            float bvv = -1e30f; int bi = 256;
            #pragma unroll
            for (int c = 0; c < 4; c++)
                #pragma unroll
                for (int jp = 0; jp < 2; jp++) {
                    float v0, v1;
                    unpack2(acc2[tt][c][jp], v0, v1);
                    float vv[2] = {v0, v1};
                    #pragma unroll
                    for (int u = 0; u < 2; u++) {
                        int i = ig*4 + c*32 + jp*2 + u;
                        float v = vv[u];
                        if (v > bvv || (v == bvv && i < bi)) { bvv = v; bi = i; }
                        float vn = -v; int i2 = 128 + i;
                        if (vn > bvv || (vn == bvv && i2 < bi)) { bvv = vn; bi = i2; }
                    }
                }
            #pragma unroll
            for (int m = 1; m < 8; m <<= 1) {
                float ov = __shfl_xor_sync(0xffffffffu, bvv, m);
                int   oi = __shfl_xor_sync(0xffffffffu, bi, m);
                if (ov > bvv || (ov == bvv && oi < bi)) { bvv = ov; bi = oi; }
            }
            if (ig == 0)
                g_bucket[(bh*NHASH + r)*NN + t0 + quad*4 + tt] = bi;
        }
    }
}

// ---------------- K3: stable counting sort per (bh, round) ------------------
__global__ __launch_bounds__(256) void sort_kernel()
{
    __shared__ __align__(16) int bks[NN];
    __shared__ int tmp[NN];
    __shared__ int hist[NBUCK];
    __shared__ int offs[NBUCK];
    __shared__ int cnt[NBUCK];
    __shared__ int wsum[8];
    int bhr = blockIdx.x;
    int tid = threadIdx.x;
    for (int t = tid; t < NN; t += 256) bks[t] = g_bucket[bhr*NN + t];
    hist[tid] = 0; cnt[tid] = 0;
    __syncthreads();
    for (int t = tid; t < NN; t += 256) atomicAdd(&hist[bks[t]], 1);
    __syncthreads();
    int hv = hist[tid];
    int incl = hv;
    #pragma unroll
    for (int d = 1; d < 32; d <<= 1) {
        int nv = __shfl_up_sync(0xffffffffu, incl, d);
        if ((tid & 31) >= d) incl += nv;
    }
    if ((tid & 31) == 31) wsum[tid >> 5] = incl;
    __syncthreads();
    if (tid == 0) {
        int s = 0;
        #pragma unroll
        for (int k = 0; k < 8; k++) { int t = wsum[k]; wsum[k] = s; s += t; }
    }
    __syncthreads();
    offs[tid] = incl - hv + wsum[tid >> 5];
    __syncthreads();
    for (int t = tid; t < NN; t += 256) {
        int b = bks[t];
        int p = atomicAdd(&cnt[b], 1);
        tmp[offs[b] + p] = t;
    }
    __syncthreads();
    {
        int o = offs[tid], k = hist[tid];
        for (int x = 1; x < k; x++) {
            int key = tmp[o + x];
            int y = x - 1;
            while (y >= 0 && tmp[o + y] > key) { tmp[o + y + 1] = tmp[o + y]; y--; }
            tmp[o + y + 1] = key;
        }
    }
    __syncthreads();
    for (int t = tid; t < NN; t += 256) g_st[bhr*NN + t] = tmp[t];
}

// ---------------- K4: chunked attention, lane-pair layout -------------------
__global__ __launch_bounds__(128) void attn_kernel()
{
    __shared__ __align__(16) float qs[4][4][68];
    __shared__ __align__(16) float ks[4][8][68];
    __shared__ int   tka[4][8];
    int w = threadIdx.x >> 5;
    int lane = threadIdx.x & 31;
    int C = blockIdx.x * 4 + w;
    int bh = C >> 10;
    int Cl = C & 1023;
    int r = Cl >> 8, c = Cl & 255;
    int Cp = (Cl + 1023) & 1023;
    int rp = Cp >> 8, cp = Cp & 255;
    int b = bh >> 3, h = bh & 7;

    if (lane < 4) {
        tka[w][lane]     = g_st[(bh*NHASH + r)*NN + c*BSZ + lane];
        tka[w][lane + 4] = g_st[(bh*NHASH + rp)*NN + cp*BSZ + lane];
    }
    __syncwarp();

    ull v2[8];
    #pragma unroll
    for (int j = 0; j < 8; j++) {
        int t = tka[w][j];
        const float* ksrc = g_qk + ((size_t)(b*NN + t))*DD + h*DHD;
        const float* vsrc = g_v  + ((size_t)(b*NN + t))*DD + h*DHD;
        float2 kp = *(const float2*)(ksrc + 2*lane);
        float2 vp = *(const float2*)(vsrc + 2*lane);
        v2[j] = pack2(vp.x, vp.y);
        if (j < 4) *(float2*)&qs[w][j][2*lane] = kp;
        float ss = kp.x*kp.x + kp.y*kp.y;
        #pragma unroll
        for (int d = 16; d >= 1; d >>= 1) ss += __shfl_xor_sync(0xffffffffu, ss, d);
        float scale = 1.0f / fmaxf(sqrtf(ss), 1e-6f);
        float2 kn; kn.x = kp.x * scale; kn.y = kp.y * scale;
        *(float2*)&ks[w][j][2*lane] = kn;
    }
    __syncwarp();

    int i = lane >> 3, j = lane & 7;
    const ulonglong2* q2 = (const ulonglong2*)qs[w][i];
    const ulonglong2* k2 = (const ulonglong2*)ks[w][j];
    ull d2 = 0ull;
    #pragma unroll
    for (int fq = 0; fq < 16; fq++) {
        ulonglong2 a = q2[fq], kk = k2[fq];
        fma2(d2, a.x, kk.x);
        fma2(d2, a.y, kk.y);
    }
    float dlo, dhi;
    unpack2(d2, dlo, dhi);
    float d = (dlo + dhi) * 0.125f;
    if (tka[w][i] == tka[w][j]) d = -5e4f;

    float m = d;
    #pragma unroll
    for (int dd = 4; dd >= 1; dd >>= 1) m = fmaxf(m, __shfl_xor_sync(0xffffffffu, m, dd));
    float e = expf(d - m);
    float s = e;
    #pragma unroll
    for (int dd = 4; dd >= 1; dd >>= 1) s += __shfl_xor_sync(0xffffffffu, s, dd);
    float lse = m + logf(s);
    float pval = e / s;

    #pragma unroll
    for (int it = 0; it < 4; it++) {
        ull acc = 0ull;
        #pragma unroll
        for (int jj = 0; jj < 8; jj++) {
            float p = __shfl_sync(0xffffffffu, pval, it*8 + jj);
            fma2(acc, pack2(p, p), v2[jj]);
        }
        *(ull*)&g_o[(((size_t)(bh*NHASH + r))*NN + tka[w][it])*DHD + 2*lane] = acc;
    }
    if (j == 0)
        g_logits[(bh*NHASH + r)*NN + tka[w][i]] = lse;
}

// ---------------- K5: combine hash rounds + merge heads ---------------------
__global__ __launch_bounds__(256) void combine_kernel()
{
    int bh = blockIdx.y;
    int t = blockIdx.x * 8 + (threadIdx.x >> 5);
    int fp = threadIdx.x & 31;
    int b = bh >> 3, h = bh & 7;
    float l[NHASH];
    #pragma unroll
    for (int r = 0; r < NHASH; r++) l[r] = g_logits[(bh*NHASH + r)*NN + t];
    float m = fmaxf(fmaxf(l[0], l[1]), fmaxf(l[2], l[3]));
    float s = 0.f;
    #pragma unroll
    for (int r = 0; r < NHASH; r++) s += expf(l[r] - m);
    ull acc = 0ull;
    #pragma unroll
    for (int r = 0; r < NHASH; r++) {
        float wr = expf(l[r] - m) / s;
        ull wd = pack2(wr, wr);
        ull vv = *(const ull*)&g_o[(((size_t)(bh*NHASH + r))*NN + t)*DHD + fp*2];
        fma2(acc, wd, vv);
    }
    *(ull*)&g_att[((size_t)(b*NN + t))*DD + h*DHD + fp*2] = acc;
}

// ---------------- launch ----------------------------------------------------
extern "C" void kernel_launch(void* const* d_in, const int* in_sizes, int n_in,
                              void* d_out, int out_size)
{
    (void)in_sizes; (void)n_in; (void)out_size;
    const float* queries = (const float*)d_in[0];
    const float* Wqk  = (const float*)d_in[3];
    const float* Wv   = (const float*)d_in[4];
    const float* Wout = (const float*)d_in[5];
    const float* bout = (const float*)d_in[6];
    const float* rot  = (const float*)d_in[7];
    float* out = (float*)d_out;

    float *qk, *v, *att;
    cudaGetSymbolAddress((void**)&qk,  g_qk);
    cudaGetSymbolAddress((void**)&v,   g_v);
    cudaGetSymbolAddress((void**)&att, g_att);

    dim3 ggrid(DD/128, MTOT/128);   // (4, 64)
    // qk GEMM stays FFMA2 fp32 (bitwise-stable bucket decisions)
    sgemm128<false><<<ggrid, 256>>>(queries, Wqk, nullptr, qk, MTOT, DD, DD);
    hash_kernel<<<dim3(NN/64, BHN), 128>>>(rot);
    sort_kernel<<<BHN*NHASH, 256>>>();
    // v GEMM on tensor cores (3xTF32): linear path, no discrete decisions
    gemm_tc<false><<<ggrid, 256>>>(queries, Wv, nullptr, v, MTOT, DD, DD);
    attn_kernel<<<(BHN*CHTOT)/4, 128>>>();
    combine_kernel<<<dim3(NN/8, BHN), 256>>>();
    // output GEMM on tensor cores (3xTF32) + bias
    gemm_tc<true><<<ggrid, 256>>>(att, Wout, bout, out, MTOT, DD, DD);
}